// round 1
// baseline (speedup 1.0000x reference)
#include <cuda_runtime.h>

#define BATCH 4
#define HH 496
#define WW 432
#define NBOX 50
#define HWPIX (HH * WW)          // 214272
#define QUADS (HWPIX / 4)        // 53568
#define SCALEF 0.8f
#define INV_SCALE 1.25f          // exact: 1/0.8

// 2-bit occupancy per (batch, pixel): bit0 = pred&orig, bit1 = pred|orig
__device__ unsigned char g_occ[BATCH * HWPIX];

// Kernel 1: channel-collapse + occupancy mask build (memory-bound; reads 27.4MB)
__global__ void occ_kernel(const float* __restrict__ added,
                           const float* __restrict__ orig,
                           float* __restrict__ out) {
    if (blockIdx.x == 0 && threadIdx.x == 0) out[0] = 0.0f;  // zero accumulator
    int i = blockIdx.x * blockDim.x + threadIdx.x;
    if (i >= BATCH * QUADS) return;
    int b = i / QUADS;
    int q = i - b * QUADS;

    const float4* ap = (const float4*)(added + (size_t)b * 4 * HWPIX);
    const float4* op = (const float4*)(orig + (size_t)b * 5 * HWPIX + HWPIX); // skip ch0

    float4 a0 = ap[q];
    float4 a1 = ap[QUADS + q];
    float4 a2 = ap[2 * QUADS + q];
    float4 a3 = ap[3 * QUADS + q];
    float4 o0 = op[q];
    float4 o1 = op[QUADS + q];
    float4 o2 = op[2 * QUADS + q];
    float4 o3 = op[3 * QUADS + q];

    float ps[4] = {a0.x + a1.x + a2.x + a3.x, a0.y + a1.y + a2.y + a3.y,
                   a0.z + a1.z + a2.z + a3.z, a0.w + a1.w + a2.w + a3.w};
    float os[4] = {o0.x + o1.x + o2.x + o3.x, o0.y + o1.y + o2.y + o3.y,
                   o0.z + o1.z + o2.z + o3.z, o0.w + o1.w + o2.w + o3.w};

    uchar4 v;
    unsigned char* vp = (unsigned char*)&v;
#pragma unroll
    for (int k = 0; k < 4; k++) {
        bool p = (ps[k] != 0.0f);
        bool o = (os[k] != 0.0f);
        vp[k] = (unsigned char)(((p && o) ? 1 : 0) | ((p || o) ? 2 : 0));
    }
    ((uchar4*)g_occ)[(size_t)b * QUADS + q] = v;
}

// Kernel 2: one block per box. Scan only the box's AABB on the grid.
__global__ void box_kernel(const float* __restrict__ boxes,
                           float* __restrict__ out) {
    int box = blockIdx.x;            // 0 .. BATCH*NBOX-1
    int b = box / NBOX;
    const float* bx = boxes + (size_t)box * 7;
    float cx = bx[0], cy = bx[1], cz = bx[2];
    float dx = bx[3], dy = bx[4], dz = bx[5], hd = bx[6];

    float hx = dx * 0.5f, hy = dy * 0.5f, hz = dz * 0.5f;
    // z test: all grid points have z=0, so it's a whole-box predicate
    if (fabsf(0.0f - cz) > hz) return;

    float c = cosf(hd), s = sinf(hd);
    float rxe = hx * fabsf(c) + hy * fabsf(s);
    float rye = hx * fabsf(s) + hy * fabsf(c);

    int r0 = max(0, (int)floorf((cx - rxe) * INV_SCALE) - 1);
    int r1 = min(HH - 1, (int)ceilf((cx + rxe) * INV_SCALE) + 1);
    int c0 = max(0, (int)floorf((cy - rye) * INV_SCALE) - 1);
    int c1 = min(WW - 1, (int)ceilf((cy + rye) * INV_SCALE) + 1);
    int nr = r1 - r0 + 1;
    int nc = c1 - c0 + 1;
    if (nr <= 0 || nc <= 0) return;
    int total = nr * nc;

    const unsigned char* occ = g_occ + (size_t)b * HWPIX;
    int inter = 0, uni = 0;
    for (int t = threadIdx.x; t < total; t += blockDim.x) {
        int rr = r0 + t / nc;
        int cc = c0 + t % nc;
        // unfused float32 math to match the reference's rounding
        float px = __fadd_rn(__fmul_rn((float)rr, SCALEF), -cx);
        float py = __fadd_rn(__fmul_rn((float)cc, SCALEF), -cy);
        float lx = __fadd_rn(__fmul_rn(px, c), __fmul_rn(py, s));
        float ly = __fadd_rn(__fmul_rn(-px, s), __fmul_rn(py, c));
        if (fabsf(lx) <= hx && fabsf(ly) <= hy) {
            unsigned char v = occ[rr * WW + cc];
            inter += (v & 1);
            uni += ((v >> 1) & 1);
        }
    }

    // block reduction: warp shuffle then shared atomics
    __shared__ int s_inter, s_uni;
    if (threadIdx.x == 0) { s_inter = 0; s_uni = 0; }
    __syncthreads();
#pragma unroll
    for (int o = 16; o > 0; o >>= 1) {
        inter += __shfl_down_sync(0xffffffffu, inter, o);
        uni   += __shfl_down_sync(0xffffffffu, uni, o);
    }
    if ((threadIdx.x & 31) == 0) {
        atomicAdd(&s_inter, inter);
        atomicAdd(&s_uni, uni);
    }
    __syncthreads();
    if (threadIdx.x == 0 && s_uni > 0) {
        float iou = (float)s_inter / (float)s_uni;
        atomicAdd(out, iou * 0.25f);   // /B
    }
}

extern "C" void kernel_launch(void* const* d_in, const int* in_sizes, int n_in,
                              void* d_out, int out_size) {
    const float* added = (const float*)d_in[0];   // [B, 4, H, W]
    const float* orig  = (const float*)d_in[1];   // [B, 5, H, W]
    const float* boxes = (const float*)d_in[2];   // [B, NB, 7]
    float* out = (float*)d_out;

    int n = BATCH * QUADS;                 // 214272 threads
    int threads = 256;
    int blocks = (n + threads - 1) / threads;
    occ_kernel<<<blocks, threads>>>(added, orig, out);
    box_kernel<<<BATCH * NBOX, 128>>>(boxes, out);
}

// round 2
// speedup vs baseline: 1.2000x; 1.2000x over previous
#include <cuda_runtime.h>

#define BATCH 4
#define HH 496
#define WW 432
#define NBOX 50
#define HWPIX (HH * WW)          // 214272
#define SCALEF 0.8f
#define INV_SCALE 1.25f          // exact: 1/0.8
#define NBLOCKS (BATCH * NBOX)   // 200

__device__ float g_sum;               // zero-initialized at load; reset each call
__device__ unsigned int g_count;

__global__ void fused_kernel(const float* __restrict__ added,
                             const float* __restrict__ orig,
                             const float* __restrict__ boxes,
                             float* __restrict__ out) {
    int box = blockIdx.x;            // 0 .. 199
    int b = box / NBOX;
    const float* bx = boxes + box * 7;
    float cx = bx[0], cy = bx[1], cz = bx[2];
    float hx = bx[3] * 0.5f, hy = bx[4] * 0.5f, hz = bx[5] * 0.5f;
    float hd = bx[6];

    int inter = 0, uni = 0;

    // z test: all grid points have z=0 -> whole-box predicate (no early return;
    // every block must reach the completion counter)
    if (fabsf(cz) <= hz) {
        float c = cosf(hd), s = sinf(hd);
        float rxe = hx * fabsf(c) + hy * fabsf(s);
        float rye = hx * fabsf(s) + hy * fabsf(c);

        int r0 = max(0, (int)floorf((cx - rxe) * INV_SCALE) - 1);
        int r1 = min(HH - 1, (int)ceilf((cx + rxe) * INV_SCALE) + 1);
        int c0 = max(0, (int)floorf((cy - rye) * INV_SCALE) - 1);
        int c1 = min(WW - 1, (int)ceilf((cy + rye) * INV_SCALE) + 1);
        int nr = r1 - r0 + 1;
        int nc = c1 - c0 + 1;
        if (nr > 0 && nc > 0) {
            int total = nr * nc;
            const float* abase = added + (size_t)b * 4 * HWPIX;
            const float* obase = orig + (size_t)b * 5 * HWPIX + HWPIX;  // skip ch0
            for (int t = threadIdx.x; t < total; t += blockDim.x) {
                int rr = r0 + t / nc;
                int cc = c0 + t - (t / nc) * nc;
                // unfused fp32 to match the reference's rounding at box edges
                float px = __fadd_rn(__fmul_rn((float)rr, SCALEF), -cx);
                float py = __fadd_rn(__fmul_rn((float)cc, SCALEF), -cy);
                float lx = __fadd_rn(__fmul_rn(px, c), __fmul_rn(py, s));
                float ly = __fadd_rn(__fmul_rn(-px, s), __fmul_rn(py, c));
                if (fabsf(lx) <= hx && fabsf(ly) <= hy) {
                    int pix = rr * WW + cc;
                    const float* a = abase + pix;
                    const float* o = obase + pix;
                    float ps = a[0] + a[HWPIX] + a[2 * HWPIX] + a[3 * HWPIX];
                    float os_ = o[0] + o[HWPIX] + o[2 * HWPIX] + o[3 * HWPIX];
                    bool p = (ps != 0.0f);
                    bool q = (os_ != 0.0f);
                    inter += (p && q) ? 1 : 0;
                    uni += (p || q) ? 1 : 0;
                }
            }
        }
    }

    // warp reduce (HW redux), then shared atomics across the 4 warps
    inter = __reduce_add_sync(0xffffffffu, inter);
    uni = __reduce_add_sync(0xffffffffu, uni);
    __shared__ int s_i, s_u;
    if (threadIdx.x == 0) { s_i = 0; s_u = 0; }
    __syncthreads();
    if ((threadIdx.x & 31) == 0) {
        atomicAdd(&s_i, inter);
        atomicAdd(&s_u, uni);
    }
    __syncthreads();

    if (threadIdx.x == 0) {
        if (s_u > 0) atomicAdd(&g_sum, (float)s_i / (float)s_u);
        __threadfence();
        unsigned int done = atomicAdd(&g_count, 1u);
        if (done == NBLOCKS - 1) {
            // last block: publish result and reset scratch for the next replay
            out[0] = atomicExch(&g_sum, 0.0f) * 0.25f;   // / B
            atomicExch(&g_count, 0u);
        }
    }
}

extern "C" void kernel_launch(void* const* d_in, const int* in_sizes, int n_in,
                              void* d_out, int out_size) {
    const float* added = (const float*)d_in[0];   // [B, 4, H, W]
    const float* orig  = (const float*)d_in[1];   // [B, 5, H, W]
    const float* boxes = (const float*)d_in[2];   // [B, NB, 7]
    float* out = (float*)d_out;
    fused_kernel<<<NBLOCKS, 128>>>(added, orig, boxes, out);
}